// round 1
// baseline (speedup 1.0000x reference)
#include <cuda_runtime.h>
#include <math.h>

#define BB 2
#define MM 8192
#define NN 8192
#define NSPLIT 8
#define TPB 256

// Scratch (no allocations allowed) --------------------------------------------
// packed (dsq_bits << 32) | idx : atomicMin gives min-dsq, tie-break min idx
__device__ unsigned long long g_best_m[BB * MM];
__device__ unsigned int       g_best_n[BB * NN];   // dsq bits (positive floats order as ints)
// 0:pos_m 1:rot 2:scale 3:opac 4:sh_dc 5:sh_rest 6:pos_n
__device__ float              g_acc[8];

// -----------------------------------------------------------------------------
__global__ void init_kernel() {
    int i = blockIdx.x * blockDim.x + threadIdx.x;
    if (i < BB * MM) g_best_m[i] = 0xFFFFFFFFFFFFFFFFull;
    if (i < BB * NN) g_best_n[i] = 0xFFFFFFFFu;
    if (i < 8) g_acc[i] = 0.0f;
}

// out -> in : per-m min distance + argmin --------------------------------------
__global__ void dist_m_kernel(const float* __restrict__ out_xyz,
                              const float* __restrict__ in_xyz) {
    __shared__ float s[TPB * 3];
    const int b = blockIdx.z;
    const int m = blockIdx.x * TPB + threadIdx.x;
    const float* op = out_xyz + ((size_t)b * MM + m) * 3;
    const float ox = op[0], oy = op[1], oz = op[2];
    const int n0 = blockIdx.y * (NN / NSPLIT);

    float best = 3.4e38f;
    int   bi   = 0;

    for (int t = 0; t < NN / NSPLIT; t += TPB) {
        const float* ip = in_xyz + ((size_t)b * NN + n0 + t) * 3;
        __syncthreads();
        for (int i = threadIdx.x; i < TPB * 3; i += TPB) s[i] = __ldg(&ip[i]);
        __syncthreads();
        #pragma unroll 16
        for (int j = 0; j < TPB; ++j) {
            float dx = s[3 * j + 0] - ox;
            float dy = s[3 * j + 1] - oy;
            float dz = s[3 * j + 2] - oz;
            float d  = fmaf(dx, dx, fmaf(dy, dy, dz * dz));
            if (d < best) { best = d; bi = n0 + t + j; }
        }
    }
    unsigned long long key =
        ((unsigned long long)__float_as_uint(best) << 32) | (unsigned)bi;
    atomicMin(&g_best_m[(size_t)b * MM + m], key);
}

// in -> out : per-n min distance ----------------------------------------------
__global__ void dist_n_kernel(const float* __restrict__ out_xyz,
                              const float* __restrict__ in_xyz) {
    __shared__ float s[TPB * 3];
    const int b = blockIdx.z;
    const int n = blockIdx.x * TPB + threadIdx.x;
    const float* ip = in_xyz + ((size_t)b * NN + n) * 3;
    const float ix = ip[0], iy = ip[1], iz = ip[2];
    const int m0 = blockIdx.y * (MM / NSPLIT);

    float best = 3.4e38f;

    for (int t = 0; t < MM / NSPLIT; t += TPB) {
        const float* op = out_xyz + ((size_t)b * MM + m0 + t) * 3;
        __syncthreads();
        for (int i = threadIdx.x; i < TPB * 3; i += TPB) s[i] = __ldg(&op[i]);
        __syncthreads();
        #pragma unroll 16
        for (int j = 0; j < TPB; ++j) {
            float dx = s[3 * j + 0] - ix;
            float dy = s[3 * j + 1] - iy;
            float dz = s[3 * j + 2] - iz;
            float d  = fmaf(dx, dx, fmaf(dy, dy, dz * dz));
            best = fminf(best, d);
        }
    }
    atomicMin(&g_best_n[(size_t)b * NN + n], __float_as_uint(best));
}

// -----------------------------------------------------------------------------
__device__ __forceinline__ float warp_sum(float v) {
    #pragma unroll
    for (int o = 16; o; o >>= 1) v += __shfl_xor_sync(0xffffffffu, v, o);
    return v;
}

__device__ __forceinline__ void block_reduce_add(float v, float* dst,
                                                 float* sh) {
    int lane = threadIdx.x & 31, w = threadIdx.x >> 5;
    v = warp_sum(v);
    if (lane == 0) sh[w] = v;
    __syncthreads();
    if (w == 0) {
        float t = (lane < TPB / 32) ? sh[lane] : 0.0f;
        t = warp_sum(t);
        if (lane == 0) atomicAdd(dst, t);
    }
    __syncthreads();
}

// per-m attribute losses + pos_m term -----------------------------------------
__global__ void loss_m_kernel(const float* __restrict__ in_rot,
                              const float* __restrict__ in_scale,
                              const float* __restrict__ in_op,
                              const float* __restrict__ in_dc,
                              const float* __restrict__ in_rest,
                              const float* __restrict__ out_rot,
                              const float* __restrict__ out_scale,
                              const float* __restrict__ out_op,
                              const float* __restrict__ out_dc,
                              const float* __restrict__ out_rest) {
    __shared__ float sh[TPB / 32];
    const int b = blockIdx.y;
    const size_t om = (size_t)b * MM + blockIdx.x * TPB + threadIdx.x;

    unsigned long long key = g_best_m[om];
    float d  = sqrtf(__uint_as_float((unsigned)(key >> 32)));
    int  idx = (int)(unsigned)(key & 0xFFFFFFFFu);
    const size_t ii = (size_t)b * NN + idx;

    float dot = 0.0f;
    #pragma unroll
    for (int c = 0; c < 4; ++c)
        dot = fmaf(out_rot[om * 4 + c], in_rot[ii * 4 + c], dot);
    float rot = 1.0f - fabsf(dot);

    float sc = 0.0f;
    #pragma unroll
    for (int c = 0; c < 3; ++c)
        sc += fabsf(out_scale[om * 3 + c] - in_scale[ii * 3 + c]);

    float op = fabsf(out_op[om] - in_op[ii]);

    float dc = 0.0f;
    #pragma unroll
    for (int c = 0; c < 3; ++c)
        dc += fabsf(out_dc[om * 3 + c] - in_dc[ii * 3 + c]);

    float rest = 0.0f;
    #pragma unroll
    for (int c = 0; c < 45; ++c)
        rest += fabsf(out_rest[om * 45 + c] - in_rest[ii * 45 + c]);

    block_reduce_add(d,    &g_acc[0], sh);
    block_reduce_add(rot,  &g_acc[1], sh);
    block_reduce_add(sc,   &g_acc[2], sh);
    block_reduce_add(op,   &g_acc[3], sh);
    block_reduce_add(dc,   &g_acc[4], sh);
    block_reduce_add(rest, &g_acc[5], sh);
}

__global__ void loss_n_kernel() {
    __shared__ float sh[TPB / 32];
    const size_t i = (size_t)blockIdx.y * NN + blockIdx.x * TPB + threadIdx.x;
    float d = sqrtf(__uint_as_float(g_best_n[i]));
    block_reduce_add(d, &g_acc[6], sh);
}

__global__ void final_kernel(float* __restrict__ out) {
    const float POS_W = 1.0f, ROT_W = 0.5f, SCALE_W = 0.5f,
                OPAC_W = 0.3f, SH_W = 0.2f;
    float pos = 0.5f * (g_acc[0] / (BB * MM) + g_acc[6] / (BB * NN));
    float total = POS_W * pos
                + ROT_W   * (g_acc[1] / (BB * MM))
                + SCALE_W * (g_acc[2] / (BB * MM * 3))
                + OPAC_W  * (g_acc[3] / (BB * MM))
                + SH_W    * (g_acc[4] / (BB * MM * 3)
                           + g_acc[5] / (BB * MM * 45));
    out[0] = total;
}

// -----------------------------------------------------------------------------
extern "C" void kernel_launch(void* const* d_in, const int* in_sizes, int n_in,
                              void* d_out, int out_size) {
    const float* in_xyz    = (const float*)d_in[0];
    const float* in_rot    = (const float*)d_in[1];
    const float* in_scale  = (const float*)d_in[2];
    const float* in_op     = (const float*)d_in[3];
    const float* in_dc     = (const float*)d_in[4];
    const float* in_rest   = (const float*)d_in[5];
    const float* out_xyz   = (const float*)d_in[6];
    const float* out_rot   = (const float*)d_in[7];
    const float* out_scale = (const float*)d_in[8];
    const float* out_op    = (const float*)d_in[9];
    const float* out_dc    = (const float*)d_in[10];
    const float* out_rest  = (const float*)d_in[11];
    float* out = (float*)d_out;

    init_kernel<<<(BB * MM + TPB - 1) / TPB, TPB>>>();

    dim3 gm(MM / TPB, NSPLIT, BB);
    dist_m_kernel<<<gm, TPB>>>(out_xyz, in_xyz);
    dim3 gn(NN / TPB, NSPLIT, BB);
    dist_n_kernel<<<gn, TPB>>>(out_xyz, in_xyz);

    dim3 glm(MM / TPB, BB);
    loss_m_kernel<<<glm, TPB>>>(in_rot, in_scale, in_op, in_dc, in_rest,
                                out_rot, out_scale, out_op, out_dc, out_rest);
    dim3 gln(NN / TPB, BB);
    loss_n_kernel<<<gln, TPB>>>();

    final_kernel<<<1, 1>>>(out);
}

// round 2
// speedup vs baseline: 1.2469x; 1.2469x over previous
#include <cuda_runtime.h>
#include <math.h>

#define BB 2
#define MM 8192
#define NN 8192
#define TPB 256
#define NSPLIT 4
#define QPT 8                 // query slots per thread
#define CPB 2048              // candidates per block (tile)
#define PPB (CPB/2)           // candidate pairs per block
#define CPW 256               // candidates per warp
#define PPW 128               // candidate pairs per warp
#define CHUNK_P 8             // pairs per tracking chunk (16 candidates)
#define NCHUNK (PPW/CHUNK_P)  // 16 chunks

// ---- scratch (no allocation allowed) ----------------------------------------
__device__ unsigned long long g_best_m[BB * MM];  // (dsq_bits<<32)|idx
__device__ unsigned int       g_best_n[BB * NN];  // dsq bits
__device__ float              g_total;

// ---- packed f32x2 helpers ---------------------------------------------------
__device__ __forceinline__ unsigned long long pk2(float lo, float hi) {
    unsigned long long r;
    asm("mov.b64 %0, {%1,%2};" : "=l"(r) : "f"(lo), "f"(hi));
    return r;
}
__device__ __forceinline__ float lo32(unsigned long long v) {
    return __uint_as_float((unsigned)(v & 0xFFFFFFFFull));
}
// e = qx*sx + qy*sy + qz*sz + nb, two lanes at once; returns both halves
__device__ __forceinline__ void ffma2_chain(
    float& e0, float& e1,
    unsigned long long qz2, unsigned long long sz2, unsigned long long nb2,
    unsigned long long qy2, unsigned long long sy2,
    unsigned long long qx2, unsigned long long sx2) {
    asm("{\n\t.reg .b64 t;\n\t"
        "fma.rn.f32x2 t, %2, %3, %4;\n\t"
        "fma.rn.f32x2 t, %5, %6, t;\n\t"
        "fma.rn.f32x2 t, %7, %8, t;\n\t"
        "mov.b64 {%0,%1}, t;\n\t}"
        : "=f"(e0), "=f"(e1)
        : "l"(qz2), "l"(sz2), "l"(nb2), "l"(qy2), "l"(sy2), "l"(qx2), "l"(sx2));
}

// -----------------------------------------------------------------------------
__global__ void init_kernel() {
    int i = blockIdx.x * blockDim.x + threadIdx.x;
    if (i < BB * MM) g_best_m[i] = 0xFFFFFFFFFFFFFFFFull;
    if (i < BB * NN) g_best_n[i] = 0xFFFFFFFFu;
    if (i == 0) g_total = 0.0f;
}

// ---- out->in: per-query max-e + exact argmax (=argmin dist) -----------------
__global__ void __launch_bounds__(TPB, 2)
dist_m_kernel(const float* __restrict__ qpts,   // out_xyz [B,M,3]
              const float* __restrict__ cpts) { // in_xyz  [B,N,3]
    __shared__ float4 tA[PPB];                  // (x0,x1,y0,y1)
    __shared__ float4 tB[PPB];                  // (z0,z1,nb0,nb1)  nb=-|c|^2/2
    __shared__ unsigned long long skey[TPB];

    const int tid = threadIdx.x;
    const int lane = tid & 31, w = tid >> 5;
    const int b = blockIdx.z;
    const int cbase = blockIdx.y * CPB;
    const int qbase = blockIdx.x * TPB;

    skey[tid] = 0xFFFFFFFFFFFFFFFFull;

    for (int p = tid; p < PPB; p += TPB) {
        const float* cp = cpts + ((size_t)b * NN + cbase + 2 * p) * 3;
        float x0 = cp[0], y0 = cp[1], z0 = cp[2];
        float x1 = cp[3], y1 = cp[4], z1 = cp[5];
        float n0 = -0.5f * fmaf(x0, x0, fmaf(y0, y0, z0 * z0));
        float n1 = -0.5f * fmaf(x1, x1, fmaf(y1, y1, z1 * z1));
        tA[p] = make_float4(x0, x1, y0, y1);
        tB[p] = make_float4(z0, z1, n0, n1);
    }

    unsigned long long qx2[QPT], qy2[QPT], qz2[QPT];
    float best[QPT];
    int bst[QPT];
    #pragma unroll
    for (int k = 0; k < QPT; ++k) {
        const float* qp = qpts + ((size_t)b * MM + qbase + k * 32 + lane) * 3;
        float x = qp[0], y = qp[1], z = qp[2];
        qx2[k] = pk2(x, x); qy2[k] = pk2(y, y); qz2[k] = pk2(z, z);
        best[k] = -3.4e38f;
        bst[k] = 0;
    }
    __syncthreads();

    const int pw = w * PPW;
    for (int ch = 0; ch < NCHUNK; ++ch) {
        float old[QPT];
        #pragma unroll
        for (int k = 0; k < QPT; ++k) old[k] = best[k];
        #pragma unroll
        for (int pp = 0; pp < CHUNK_P; ++pp) {
            int p = pw + ch * CHUNK_P + pp;
            float4 A = tA[p], Bv = tB[p];
            unsigned long long sx2 = pk2(A.x, A.y), sy2 = pk2(A.z, A.w);
            unsigned long long sz2 = pk2(Bv.x, Bv.y), nb2 = pk2(Bv.z, Bv.w);
            #pragma unroll
            for (int k = 0; k < QPT; ++k) {
                float e0, e1;
                ffma2_chain(e0, e1, qz2[k], sz2, nb2, qy2[k], sy2, qx2[k], sx2);
                best[k] = fmaxf(best[k], fmaxf(e0, e1));
            }
        }
        #pragma unroll
        for (int k = 0; k < QPT; ++k)
            if (best[k] > old[k]) bst[k] = ch;
    }

    // exact first-index recovery inside the winning 16-candidate window
    #pragma unroll 1
    for (int k = 0; k < QPT; ++k) {
        float qx = lo32(qx2[k]), qy = lo32(qy2[k]), qz = lo32(qz2[k]);
        int c0 = bst[k] * (CHUNK_P * 2);
        int found = 0; bool got = false;
        #pragma unroll 1
        for (int j = 0; j < CHUNK_P * 2; ++j) {
            int c = c0 + j, p = pw + (c >> 1), h = c & 1;
            float4 A = tA[p], Bv = tB[p];
            float sx = h ? A.y : A.x;
            float sy = h ? A.w : A.z;
            float sz = h ? Bv.y : Bv.x;
            float nb = h ? Bv.w : Bv.z;
            float e = fmaf(qx, sx, fmaf(qy, sy, fmaf(qz, sz, nb)));
            if (!got && e == best[k]) { found = j; got = true; }
        }
        float so  = fmaf(qx, qx, fmaf(qy, qy, qz * qz));
        float dsq = fmaxf(fmaf(-2.0f, best[k], so), 0.0f);
        unsigned gidx = (unsigned)(cbase + w * CPW + c0 + found);
        unsigned long long key =
            ((unsigned long long)__float_as_uint(dsq) << 32) | gidx;
        atomicMin(&skey[k * 32 + lane], key);
    }
    __syncthreads();
    atomicMin(&g_best_m[(size_t)b * MM + qbase + tid], skey[tid]);
}

// ---- in->out: per-query min distance only -----------------------------------
__global__ void __launch_bounds__(TPB, 2)
dist_n_kernel(const float* __restrict__ qpts,   // in_xyz  [B,N,3]
              const float* __restrict__ cpts) { // out_xyz [B,M,3]
    __shared__ float4 tA[PPB];
    __shared__ float4 tB[PPB];
    __shared__ unsigned int smin[TPB];

    const int tid = threadIdx.x;
    const int lane = tid & 31, w = tid >> 5;
    const int b = blockIdx.z;
    const int cbase = blockIdx.y * CPB;
    const int qbase = blockIdx.x * TPB;

    smin[tid] = 0xFFFFFFFFu;

    for (int p = tid; p < PPB; p += TPB) {
        const float* cp = cpts + ((size_t)b * MM + cbase + 2 * p) * 3;
        float x0 = cp[0], y0 = cp[1], z0 = cp[2];
        float x1 = cp[3], y1 = cp[4], z1 = cp[5];
        float n0 = -0.5f * fmaf(x0, x0, fmaf(y0, y0, z0 * z0));
        float n1 = -0.5f * fmaf(x1, x1, fmaf(y1, y1, z1 * z1));
        tA[p] = make_float4(x0, x1, y0, y1);
        tB[p] = make_float4(z0, z1, n0, n1);
    }

    unsigned long long qx2[QPT], qy2[QPT], qz2[QPT];
    float best[QPT];
    #pragma unroll
    for (int k = 0; k < QPT; ++k) {
        const float* qp = qpts + ((size_t)b * NN + qbase + k * 32 + lane) * 3;
        float x = qp[0], y = qp[1], z = qp[2];
        qx2[k] = pk2(x, x); qy2[k] = pk2(y, y); qz2[k] = pk2(z, z);
        best[k] = -3.4e38f;
    }
    __syncthreads();

    const int pw = w * PPW;
    #pragma unroll 4
    for (int p = pw; p < pw + PPW; ++p) {
        float4 A = tA[p], Bv = tB[p];
        unsigned long long sx2 = pk2(A.x, A.y), sy2 = pk2(A.z, A.w);
        unsigned long long sz2 = pk2(Bv.x, Bv.y), nb2 = pk2(Bv.z, Bv.w);
        #pragma unroll
        for (int k = 0; k < QPT; ++k) {
            float e0, e1;
            ffma2_chain(e0, e1, qz2[k], sz2, nb2, qy2[k], sy2, qx2[k], sx2);
            best[k] = fmaxf(best[k], fmaxf(e0, e1));
        }
    }

    #pragma unroll
    for (int k = 0; k < QPT; ++k) {
        float qx = lo32(qx2[k]), qy = lo32(qy2[k]), qz = lo32(qz2[k]);
        float so  = fmaf(qx, qx, fmaf(qy, qy, qz * qz));
        float dsq = fmaxf(fmaf(-2.0f, best[k], so), 0.0f);
        atomicMin(&smin[k * 32 + lane], __float_as_uint(dsq));
    }
    __syncthreads();
    atomicMin(&g_best_n[(size_t)b * NN + qbase + tid], smin[tid]);
}

// -----------------------------------------------------------------------------
__device__ __forceinline__ float warp_sum(float v) {
    #pragma unroll
    for (int o = 16; o; o >>= 1) v += __shfl_xor_sync(0xffffffffu, v, o);
    return v;
}

// warp per query: gather + all weighted loss terms into one accumulator
__global__ void loss_m_kernel(const float* __restrict__ in_rot,
                              const float* __restrict__ in_scale,
                              const float* __restrict__ in_op,
                              const float* __restrict__ in_dc,
                              const float* __restrict__ in_rest,
                              const float* __restrict__ out_rot,
                              const float* __restrict__ out_scale,
                              const float* __restrict__ out_op,
                              const float* __restrict__ out_dc,
                              const float* __restrict__ out_rest) {
    __shared__ float sw[8];
    const int lane = threadIdx.x & 31, w = threadIdx.x >> 5;
    const size_t om = (size_t)blockIdx.x * 8 + w;      // global over B*M
    const int b = (int)(om / MM);

    unsigned long long key = g_best_m[om];
    float d = sqrtf(__uint_as_float((unsigned)(key >> 32)));
    unsigned idx = (unsigned)(key & 0xFFFFFFFFu);
    const size_t ii = (size_t)b * NN + idx;

    const float W_POSM = 0.5f / (BB * MM);
    const float W_ROT  = 0.5f / (BB * MM);
    const float W_SC   = 0.5f / (BB * MM * 3);
    const float W_OP   = 0.3f / (BB * MM);
    const float W_DC   = 0.2f / (BB * MM * 3);
    const float W_RST  = 0.2f / (BB * MM * 45);

    float c = 0.0f;
    if (lane < 45)  // always true for lane<32; kept for clarity
        c += W_RST * fabsf(out_rest[om * 45 + lane] - in_rest[ii * 45 + lane]);
    if (lane < 13)
        c += W_RST * fabsf(out_rest[om * 45 + 32 + lane] -
                           in_rest[ii * 45 + 32 + lane]);
    if (lane < 3) {
        c += W_SC * fabsf(out_scale[om * 3 + lane] - in_scale[ii * 3 + lane]);
        c += W_DC * fabsf(out_dc[om * 3 + lane]    - in_dc[ii * 3 + lane]);
    }
    if (lane == 0) {
        float dot = 0.0f;
        #pragma unroll
        for (int j = 0; j < 4; ++j)
            dot = fmaf(out_rot[om * 4 + j], in_rot[ii * 4 + j], dot);
        c += W_ROT * (1.0f - fabsf(dot));
        c += W_OP * fabsf(out_op[om] - in_op[ii]);
        c += W_POSM * d;
    }
    c = warp_sum(c);
    if (lane == 0) sw[w] = c;
    __syncthreads();
    if (threadIdx.x == 0) {
        float t = 0.0f;
        #pragma unroll
        for (int j = 0; j < 8; ++j) t += sw[j];
        atomicAdd(&g_total, t);
    }
}

__global__ void loss_n_kernel() {
    __shared__ float sw[TPB / 32];
    const int lane = threadIdx.x & 31, w = threadIdx.x >> 5;
    const size_t i = (size_t)blockIdx.x * TPB + threadIdx.x;  // over B*N
    float d = sqrtf(__uint_as_float(g_best_n[i]));
    float c = (0.5f / (BB * NN)) * d;
    c = warp_sum(c);
    if (lane == 0) sw[w] = c;
    __syncthreads();
    if (threadIdx.x == 0) {
        float t = 0.0f;
        #pragma unroll
        for (int j = 0; j < TPB / 32; ++j) t += sw[j];
        atomicAdd(&g_total, t);
    }
}

__global__ void final_kernel(float* __restrict__ out) {
    out[0] = g_total;
}

// -----------------------------------------------------------------------------
extern "C" void kernel_launch(void* const* d_in, const int* in_sizes, int n_in,
                              void* d_out, int out_size) {
    const float* in_xyz    = (const float*)d_in[0];
    const float* in_rot    = (const float*)d_in[1];
    const float* in_scale  = (const float*)d_in[2];
    const float* in_op     = (const float*)d_in[3];
    const float* in_dc     = (const float*)d_in[4];
    const float* in_rest   = (const float*)d_in[5];
    const float* out_xyz   = (const float*)d_in[6];
    const float* out_rot   = (const float*)d_in[7];
    const float* out_scale = (const float*)d_in[8];
    const float* out_op    = (const float*)d_in[9];
    const float* out_dc    = (const float*)d_in[10];
    const float* out_rest  = (const float*)d_in[11];
    float* out = (float*)d_out;

    init_kernel<<<(BB * MM + TPB - 1) / TPB, TPB>>>();

    dim3 gm(MM / TPB, NSPLIT, BB);
    dist_m_kernel<<<gm, TPB>>>(out_xyz, in_xyz);
    dim3 gn(NN / TPB, NSPLIT, BB);
    dist_n_kernel<<<gn, TPB>>>(in_xyz, out_xyz);

    loss_m_kernel<<<BB * MM / 8, TPB>>>(in_rot, in_scale, in_op, in_dc,
                                        in_rest, out_rot, out_scale, out_op,
                                        out_dc, out_rest);
    loss_n_kernel<<<BB * NN / TPB, TPB>>>();
    final_kernel<<<1, 1>>>(out);
}

// round 3
// speedup vs baseline: 1.8552x; 1.4878x over previous
#include <cuda_runtime.h>
#include <math.h>

#define BB 2
#define MM 8192
#define NN 8192
#define TPB 256
#define NSPLIT 4
#define QPT 8                 // queries per thread
#define CPB 2048              // candidates per block tile
#define PPB (CPB/2)           // candidate pairs per block
#define CPW 256               // candidates per warp
#define PPW 128               // pairs per warp
#define CHUNK_P 4             // pairs per tracking chunk (8 candidates)
#define NCHUNK (PPW/CHUNK_P)  // 32 chunks

// ---- scratch ----------------------------------------------------------------
__device__ unsigned long long g_best_m[BB * MM];  // (dsq_bits<<32)|idx
__device__ unsigned int       g_best_n[BB * NN];  // dsq bits
__device__ float              g_accs[32 * 32];    // spread accumulators, 128B stride

// ---- packed f32x2 helpers ---------------------------------------------------
__device__ __forceinline__ unsigned long long pk2(float lo, float hi) {
    unsigned long long r;
    asm("mov.b64 %0, {%1,%2};" : "=l"(r) : "f"(lo), "f"(hi));
    return r;
}
__device__ __forceinline__ float lo32(unsigned long long v) {
    return __uint_as_float((unsigned)(v & 0xFFFFFFFFull));
}
// e = qx*sx + qy*sy + qz*sz + nb on both packed halves
__device__ __forceinline__ void ffma2_chain(
    float& e0, float& e1,
    unsigned long long qz2, unsigned long long sz2, unsigned long long nb2,
    unsigned long long qy2, unsigned long long sy2,
    unsigned long long qx2, unsigned long long sx2) {
    asm("{\n\t.reg .b64 t;\n\t"
        "fma.rn.f32x2 t, %2, %3, %4;\n\t"
        "fma.rn.f32x2 t, %5, %6, t;\n\t"
        "fma.rn.f32x2 t, %7, %8, t;\n\t"
        "mov.b64 {%0,%1}, t;\n\t}"
        : "=f"(e0), "=f"(e1)
        : "l"(qz2), "l"(sz2), "l"(nb2), "l"(qy2), "l"(sy2), "l"(qx2), "l"(sx2));
}

// -----------------------------------------------------------------------------
__global__ void init_kernel() {
    int i = blockIdx.x * blockDim.x + threadIdx.x;
    if (i < BB * MM) g_best_m[i] = 0xFFFFFFFFFFFFFFFFull;
    if (i < BB * NN) g_best_n[i] = 0xFFFFFFFFu;
    if (i < 32 * 32) g_accs[i] = 0.0f;
}

// ---- fused distance scan: dir 0 = out->in (argmin), dir 1 = in->out (min) ---
__global__ void __launch_bounds__(TPB, 2)
dist_kernel(const float* __restrict__ out_xyz,
            const float* __restrict__ in_xyz) {
    __shared__ unsigned long long sX[PPB], sY[PPB], sZ[PPB], sNB[PPB];
    __shared__ unsigned long long skey[TPB];

    const int tid = threadIdx.x;
    const int lane = tid & 31, w = tid >> 5;
    const int dir = blockIdx.z & 1;
    const int b = blockIdx.z >> 1;
    const float* qpts = dir ? in_xyz : out_xyz;
    const float* cpts = dir ? out_xyz : in_xyz;
    const int cbase = blockIdx.y * CPB;
    const int qbase = blockIdx.x * TPB;

    skey[tid] = 0xFFFFFFFFFFFFFFFFull;

    // load candidate tile, packed two-per-u64: (even, odd)
    #pragma unroll
    for (int p = tid; p < PPB; p += TPB) {
        const float2* cp =
            (const float2*)(cpts + ((size_t)b * NN + cbase + 2 * p) * 3);
        float2 f0 = __ldg(cp + 0);   // x0 y0
        float2 f1 = __ldg(cp + 1);   // z0 x1
        float2 f2 = __ldg(cp + 2);   // y1 z1
        float n0 = -0.5f * fmaf(f0.x, f0.x, fmaf(f0.y, f0.y, f1.x * f1.x));
        float n1 = -0.5f * fmaf(f1.y, f1.y, fmaf(f2.x, f2.x, f2.y * f2.y));
        sX[p]  = pk2(f0.x, f1.y);
        sY[p]  = pk2(f0.y, f2.x);
        sZ[p]  = pk2(f1.x, f2.y);
        sNB[p] = pk2(n0, n1);
    }

    unsigned long long qx2[QPT], qy2[QPT], qz2[QPT];
    float best[QPT];
    #pragma unroll
    for (int k = 0; k < QPT; ++k) {
        const float* qp = qpts + ((size_t)b * MM + qbase + k * 32 + lane) * 3;
        float x = qp[0], y = qp[1], z = qp[2];
        qx2[k] = pk2(x, x); qy2[k] = pk2(y, y); qz2[k] = pk2(z, z);
        best[k] = -3.4e38f;
    }
    __syncthreads();

    const int pw = w * PPW;

    if (dir == 0) {
        // ---- out->in: max-e with chunk tracking for exact argmin ------------
        int bst[QPT];
        #pragma unroll
        for (int k = 0; k < QPT; ++k) bst[k] = 0;

        for (int ch = 0; ch < NCHUNK; ++ch) {
            float old[QPT];
            #pragma unroll
            for (int k = 0; k < QPT; ++k) old[k] = best[k];
            #pragma unroll
            for (int pp = 0; pp < CHUNK_P; ++pp) {
                int p = pw + ch * CHUNK_P + pp;
                unsigned long long sx2 = sX[p], sy2 = sY[p];
                unsigned long long sz2 = sZ[p], nb2 = sNB[p];
                #pragma unroll
                for (int k = 0; k < QPT; ++k) {
                    float e0, e1;
                    ffma2_chain(e0, e1, qz2[k], sz2, nb2, qy2[k], sy2,
                                qx2[k], sx2);
                    best[k] = fmaxf(best[k], fmaxf(e0, e1));
                }
            }
            #pragma unroll
            for (int k = 0; k < QPT; ++k)
                if (best[k] > old[k]) bst[k] = ch;
        }

        // exact first-index recovery inside winning 8-candidate window
        const float* fX  = (const float*)sX;
        const float* fY  = (const float*)sY;
        const float* fZ  = (const float*)sZ;
        const float* fNB = (const float*)sNB;
        #pragma unroll 1
        for (int k = 0; k < QPT; ++k) {
            float qx = lo32(qx2[k]), qy = lo32(qy2[k]), qz = lo32(qz2[k]);
            int base = w * CPW + bst[k] * (CHUNK_P * 2);
            int found = 0;
            #pragma unroll
            for (int j = CHUNK_P * 2 - 1; j >= 0; --j) {   // descending: first match wins
                float e = fmaf(qx, fX[base + j],
                          fmaf(qy, fY[base + j],
                          fmaf(qz, fZ[base + j], fNB[base + j])));
                found = (e == best[k]) ? j : found;
            }
            float so  = fmaf(qx, qx, fmaf(qy, qy, qz * qz));
            float dsq = fmaxf(fmaf(-2.0f, best[k], so), 0.0f);
            unsigned gidx = (unsigned)(cbase + base + found);
            unsigned long long key =
                ((unsigned long long)__float_as_uint(dsq) << 32) | gidx;
            atomicMin(&skey[k * 32 + lane], key);
        }
        __syncthreads();
        atomicMin(&g_best_m[(size_t)b * MM + qbase + tid], skey[tid]);
    } else {
        // ---- in->out: min distance only -------------------------------------
        #pragma unroll 4
        for (int p = pw; p < pw + PPW; ++p) {
            unsigned long long sx2 = sX[p], sy2 = sY[p];
            unsigned long long sz2 = sZ[p], nb2 = sNB[p];
            #pragma unroll
            for (int k = 0; k < QPT; ++k) {
                float e0, e1;
                ffma2_chain(e0, e1, qz2[k], sz2, nb2, qy2[k], sy2,
                            qx2[k], sx2);
                best[k] = fmaxf(best[k], fmaxf(e0, e1));
            }
        }
        #pragma unroll
        for (int k = 0; k < QPT; ++k) {
            float qx = lo32(qx2[k]), qy = lo32(qy2[k]), qz = lo32(qz2[k]);
            float so  = fmaf(qx, qx, fmaf(qy, qy, qz * qz));
            float dsq = fmaxf(fmaf(-2.0f, best[k], so), 0.0f);
            atomicMin(&skey[k * 32 + lane],
                      (unsigned long long)__float_as_uint(dsq) << 32);
        }
        __syncthreads();
        atomicMin(&g_best_n[(size_t)b * NN + qbase + tid],
                  (unsigned)(skey[tid] >> 32));
    }
}

// -----------------------------------------------------------------------------
__device__ __forceinline__ float warp_sum(float v) {
    #pragma unroll
    for (int o = 16; o; o >>= 1) v += __shfl_xor_sync(0xffffffffu, v, o);
    return v;
}

// warp per query: gather + all weighted loss terms, spread-slot accumulation
__global__ void loss_m_kernel(const float* __restrict__ in_rot,
                              const float* __restrict__ in_scale,
                              const float* __restrict__ in_op,
                              const float* __restrict__ in_dc,
                              const float* __restrict__ in_rest,
                              const float* __restrict__ out_rot,
                              const float* __restrict__ out_scale,
                              const float* __restrict__ out_op,
                              const float* __restrict__ out_dc,
                              const float* __restrict__ out_rest) {
    __shared__ float sw[8];
    const int lane = threadIdx.x & 31, w = threadIdx.x >> 5;
    const size_t om = (size_t)blockIdx.x * 8 + w;      // global over B*M
    const int b = (int)(om / MM);

    unsigned long long key = g_best_m[om];
    float d = sqrtf(__uint_as_float((unsigned)(key >> 32)));
    unsigned idx = (unsigned)(key & 0xFFFFFFFFu);
    const size_t ii = (size_t)b * NN + idx;

    const float W_POSM = 0.5f / (BB * MM);
    const float W_ROT  = 0.5f / (BB * MM);
    const float W_SC   = 0.5f / (BB * MM * 3);
    const float W_OP   = 0.3f / (BB * MM);
    const float W_DC   = 0.2f / (BB * MM * 3);
    const float W_RST  = 0.2f / (BB * MM * 45);

    float c = W_RST * fabsf(out_rest[om * 45 + lane] - in_rest[ii * 45 + lane]);
    if (lane < 13)
        c += W_RST * fabsf(out_rest[om * 45 + 32 + lane] -
                           in_rest[ii * 45 + 32 + lane]);
    if (lane < 3) {
        c += W_SC * fabsf(out_scale[om * 3 + lane] - in_scale[ii * 3 + lane]);
        c += W_DC * fabsf(out_dc[om * 3 + lane]    - in_dc[ii * 3 + lane]);
    }
    if (lane == 0) {
        float dot = 0.0f;
        #pragma unroll
        for (int j = 0; j < 4; ++j)
            dot = fmaf(out_rot[om * 4 + j], in_rot[ii * 4 + j], dot);
        c += W_ROT * (1.0f - fabsf(dot));
        c += W_OP * fabsf(out_op[om] - in_op[ii]);
        c += W_POSM * d;
    }
    c = warp_sum(c);
    if (lane == 0) sw[w] = c;
    __syncthreads();
    if (threadIdx.x == 0) {
        float t = 0.0f;
        #pragma unroll
        for (int j = 0; j < 8; ++j) t += sw[j];
        atomicAdd(&g_accs[(blockIdx.x & 31) * 32], t);
    }
}

__global__ void loss_n_kernel() {
    __shared__ float sw[TPB / 32];
    const int lane = threadIdx.x & 31, w = threadIdx.x >> 5;
    const size_t i = (size_t)blockIdx.x * TPB + threadIdx.x;  // over B*N
    float d = sqrtf(__uint_as_float(g_best_n[i]));
    float c = (0.5f / (BB * NN)) * d;
    c = warp_sum(c);
    if (lane == 0) sw[w] = c;
    __syncthreads();
    if (threadIdx.x == 0) {
        float t = 0.0f;
        #pragma unroll
        for (int j = 0; j < TPB / 32; ++j) t += sw[j];
        atomicAdd(&g_accs[(blockIdx.x & 31) * 32], t);
    }
}

__global__ void final_kernel(float* __restrict__ out) {
    float v = g_accs[threadIdx.x * 32];   // 32 threads, one slot each
    v = warp_sum(v);
    if (threadIdx.x == 0) out[0] = v;
}

// -----------------------------------------------------------------------------
extern "C" void kernel_launch(void* const* d_in, const int* in_sizes, int n_in,
                              void* d_out, int out_size) {
    const float* in_xyz    = (const float*)d_in[0];
    const float* in_rot    = (const float*)d_in[1];
    const float* in_scale  = (const float*)d_in[2];
    const float* in_op     = (const float*)d_in[3];
    const float* in_dc     = (const float*)d_in[4];
    const float* in_rest   = (const float*)d_in[5];
    const float* out_xyz   = (const float*)d_in[6];
    const float* out_rot   = (const float*)d_in[7];
    const float* out_scale = (const float*)d_in[8];
    const float* out_op    = (const float*)d_in[9];
    const float* out_dc    = (const float*)d_in[10];
    const float* out_rest  = (const float*)d_in[11];
    float* out = (float*)d_out;

    init_kernel<<<(BB * MM + TPB - 1) / TPB, TPB>>>();

    dim3 g(MM / TPB, NSPLIT, BB * 2);
    dist_kernel<<<g, TPB>>>(out_xyz, in_xyz);

    loss_m_kernel<<<BB * MM / 8, TPB>>>(in_rot, in_scale, in_op, in_dc,
                                        in_rest, out_rot, out_scale, out_op,
                                        out_dc, out_rest);
    loss_n_kernel<<<BB * NN / TPB, TPB>>>();
    final_kernel<<<1, 32>>>(out);
}